// round 16
// baseline (speedup 1.0000x reference)
#include <cuda_runtime.h>
#include <cuda_fp16.h>
#include <cstdint>

#define BATCH 8
#define SEQ   2048
#define EMB   256
#define QD    512
#define VD    512
#define MTOT  (BATCH*SEQ)   // 16384

#define BKH    32                 // k-elements (halfs) per tile
#define STAGES 4
#define ROWB   80                 // smem row bytes: 64 data + 16 pad (conflict-free)
#define TILE_B (128*ROWB)         // 10240 B per stage per operand
#define GSMEM  (STAGES*2*TILE_B)  // 81920 B
#define GTHR   128                // qk/pv: 4 warps, 2x2 grid of 64x64 warp tiles

// ---------------- scratch (device globals; allocation-free) ----------------
__device__ __half g_x [(size_t)MTOT*EMB];        // x in fp16
__device__ __half g_wt[(size_t)3*QD*EMB];        // W^T fp16: [z][n][k]
__device__ __half g_q [(size_t)MTOT*QD];
__device__ __half g_k [(size_t)MTOT*QD];
__device__ __half g_vt[(size_t)BATCH*VD*SEQ];    // V^T fp16: [b][v][s]
__device__ __half g_p [(size_t)BATCH*SEQ*SEQ];   // UNNORMALIZED probs fp16
__device__ float  g_rowsum[(size_t)MTOT];        // per-row sum of exp

template<int N> struct IC { static constexpr int value = N; };

// ---------------- helpers ----------------
__device__ __forceinline__ void mma16(float c[4], const uint32_t a[4], const uint32_t b[2]){
  asm volatile(
    "mma.sync.aligned.m16n8k16.row.col.f32.f16.f16.f32 "
    "{%0,%1,%2,%3}, {%4,%5,%6,%7}, {%8,%9}, {%0,%1,%2,%3};"
    : "+f"(c[0]), "+f"(c[1]), "+f"(c[2]), "+f"(c[3])
    : "r"(a[0]), "r"(a[1]), "r"(a[2]), "r"(a[3]), "r"(b[0]), "r"(b[1]));
}
template<int IMM>
__device__ __forceinline__ void ldsm4o(uint32_t& r0, uint32_t& r1, uint32_t& r2, uint32_t& r3,
                                       uint32_t addr){
  asm volatile("ldmatrix.sync.aligned.m8n8.x4.shared.b16 {%0,%1,%2,%3}, [%4+%5];"
    : "=r"(r0), "=r"(r1), "=r"(r2), "=r"(r3) : "r"(addr), "n"(IMM));
}
__device__ __forceinline__ void cp16(uint32_t dst, const void* src){
  asm volatile("cp.async.ca.shared.global [%0], [%1], 16;" :: "r"(dst), "l"(src) : "memory");
}
__device__ __forceinline__ void cp_commit(){
  asm volatile("cp.async.commit_group;" ::: "memory");
}
template<int N> __device__ __forceinline__ void cp_wait(){
  asm volatile("cp.async.wait_group %0;" :: "n"(N) : "memory");
}

// ---------------- fp16 GEMM core, 128 threads (qk/pv) -------------------------
__device__ __forceinline__ void gemm_fp16_core(
    const __half* __restrict__ A, int lda,
    const __half* __restrict__ B, int ldb,
    int KT, char* smem, float acc[4][8][4])
{
  const int tid  = threadIdx.x;
  const int lane = tid & 31, warp = tid >> 5;
  const int mB = (warp & 1)*64, nB = (warp >> 1)*64;
  const int lrow  = lane & 15;
  const int lkoff = (lane >> 4)*16;

  const uint32_t sA = (uint32_t)__cvta_generic_to_shared(smem);
  const uint32_t sB = sA + STAGES*TILE_B;

  uint32_t aAddr[4], bAddr[4];
  #pragma unroll
  for (int mi = 0; mi < 4; mi++)
    aAddr[mi] = sA + (mB + mi*16 + lrow)*ROWB + lkoff;
  #pragma unroll
  for (int nn = 0; nn < 4; nn++)
    bAddr[nn] = sB + (nB + nn*16 + lrow)*ROWB + lkoff;

  const int cr0 = tid >> 2, cc0 = (tid & 3);
  const __half* aG0 = A + (size_t)cr0*lda + cc0*8;
  const __half* bG0 = B + (size_t)cr0*ldb + cc0*8;
  const int cr1 = (tid + 128) >> 2, cc1 = ((tid + 128) & 3);
  const __half* aG1 = A + (size_t)cr1*lda + cc1*8;
  const __half* bG1 = B + (size_t)cr1*ldb + cc1*8;
  const int cr2 = (tid + 256) >> 2, cc2 = ((tid + 256) & 3);
  const __half* aG2 = A + (size_t)cr2*lda + cc2*8;
  const __half* bG2 = B + (size_t)cr2*ldb + cc2*8;
  const int cr3 = (tid + 384) >> 2, cc3 = ((tid + 384) & 3);
  const __half* aG3 = A + (size_t)cr3*lda + cc3*8;
  const __half* bG3 = B + (size_t)cr3*ldb + cc3*8;
  const uint32_t so0 = cr0*ROWB + cc0*16;
  const uint32_t so1 = cr1*ROWB + cc1*16;
  const uint32_t so2 = cr2*ROWB + cc2*16;
  const uint32_t so3 = cr3*ROWB + cc3*16;

  auto issue = [&](int kt){
    int st = kt & (STAGES-1);
    uint32_t da = sA + st*TILE_B, db = sB + st*TILE_B;
    int ko = kt*BKH;
    cp16(da + so0, aG0 + ko); cp16(db + so0, bG0 + ko);
    cp16(da + so1, aG1 + ko); cp16(db + so1, bG1 + ko);
    cp16(da + so2, aG2 + ko); cp16(db + so2, bG2 + ko);
    cp16(da + so3, aG3 + ko); cp16(db + so3, bG3 + ko);
  };

  auto compute = [&](auto stc){
    constexpr int S0 = decltype(stc)::value * TILE_B;
    {
      uint32_t ah[4][4];
      ldsm4o<S0>(ah[0][0], ah[0][1], ah[0][2], ah[0][3], aAddr[0]);
      ldsm4o<S0>(ah[1][0], ah[1][1], ah[1][2], ah[1][3], aAddr[1]);
      ldsm4o<S0>(ah[2][0], ah[2][1], ah[2][2], ah[2][3], aAddr[2]);
      ldsm4o<S0>(ah[3][0], ah[3][1], ah[3][2], ah[3][3], aAddr[3]);
      uint32_t bh[8][2];
      ldsm4o<S0>(bh[0][0], bh[1][0], bh[0][1], bh[1][1], bAddr[0]);
      ldsm4o<S0>(bh[2][0], bh[3][0], bh[2][1], bh[3][1], bAddr[1]);
      ldsm4o<S0>(bh[4][0], bh[5][0], bh[4][1], bh[5][1], bAddr[2]);
      ldsm4o<S0>(bh[6][0], bh[7][0], bh[6][1], bh[7][1], bAddr[3]);
      #pragma unroll
      for (int mi = 0; mi < 4; mi++)
        #pragma unroll
        for (int ni = 0; ni < 8; ni++)
          mma16(acc[mi][ni], ah[mi], bh[ni]);
    }
    {
      uint32_t ah[4][4];
      ldsm4o<S0+32>(ah[0][0], ah[0][1], ah[0][2], ah[0][3], aAddr[0]);
      ldsm4o<S0+32>(ah[1][0], ah[1][1], ah[1][2], ah[1][3], aAddr[1]);
      ldsm4o<S0+32>(ah[2][0], ah[2][1], ah[2][2], ah[2][3], aAddr[2]);
      ldsm4o<S0+32>(ah[3][0], ah[3][1], ah[3][2], ah[3][3], aAddr[3]);
      uint32_t bh[8][2];
      ldsm4o<S0+32>(bh[0][0], bh[1][0], bh[0][1], bh[1][1], bAddr[0]);
      ldsm4o<S0+32>(bh[2][0], bh[3][0], bh[2][1], bh[3][1], bAddr[1]);
      ldsm4o<S0+32>(bh[4][0], bh[5][0], bh[4][1], bh[5][1], bAddr[2]);
      ldsm4o<S0+32>(bh[6][0], bh[7][0], bh[6][1], bh[7][1], bAddr[3]);
      #pragma unroll
      for (int mi = 0; mi < 4; mi++)
        #pragma unroll
        for (int ni = 0; ni < 8; ni++)
          mma16(acc[mi][ni], ah[mi], bh[ni]);
    }
  };

  #pragma unroll
  for (int s = 0; s < STAGES-1; s++){
    if (s < KT) issue(s);
    cp_commit();
  }
  for (int kt = 0; kt < KT; kt += 4){
    cp_wait<STAGES-2>(); __syncthreads();
    if (kt + 3 < KT) issue(kt + 3);
    cp_commit();
    compute(IC<0>{});
    cp_wait<STAGES-2>(); __syncthreads();
    if (kt + 4 < KT) issue(kt + 4);
    cp_commit();
    compute(IC<1>{});
    cp_wait<STAGES-2>(); __syncthreads();
    if (kt + 5 < KT) issue(kt + 5);
    cp_commit();
    compute(IC<2>{});
    cp_wait<STAGES-2>(); __syncthreads();
    if (kt + 6 < KT) issue(kt + 6);
    cp_commit();
    compute(IC<3>{});
  }
}

// ---------------- fp16 GEMM core, 256 threads (proj: short K) -----------------
__device__ __forceinline__ void gemm_fp16_core256(
    const __half* __restrict__ A, int lda,
    const __half* __restrict__ B, int ldb,
    int KT, char* smem, float acc[4][4][4])
{
  const int tid  = threadIdx.x;
  const int lane = tid & 31, warp = tid >> 5;
  const int mB = (warp & 1)*64, nB = (warp >> 1)*32;
  const int lrow  = lane & 15;
  const int lkoff = (lane >> 4)*16;

  const uint32_t sA = (uint32_t)__cvta_generic_to_shared(smem);
  const uint32_t sB = sA + STAGES*TILE_B;

  uint32_t aAddr[4], bAddr[2];
  #pragma unroll
  for (int mi = 0; mi < 4; mi++)
    aAddr[mi] = sA + (mB + mi*16 + lrow)*ROWB + lkoff;
  #pragma unroll
  for (int nn = 0; nn < 2; nn++)
    bAddr[nn] = sB + (nB + nn*16 + lrow)*ROWB + lkoff;

  const int cr0 = tid >> 2, cc0 = (tid & 3);
  const __half* aG0 = A + (size_t)cr0*lda + cc0*8;
  const __half* bG0 = B + (size_t)cr0*ldb + cc0*8;
  const int cr1 = (tid + 256) >> 2, cc1 = ((tid + 256) & 3);
  const __half* aG1 = A + (size_t)cr1*lda + cc1*8;
  const __half* bG1 = B + (size_t)cr1*ldb + cc1*8;
  const uint32_t so0 = cr0*ROWB + cc0*16;
  const uint32_t so1 = cr1*ROWB + cc1*16;

  auto issue = [&](int kt){
    int st = kt & (STAGES-1);
    uint32_t da = sA + st*TILE_B, db = sB + st*TILE_B;
    int ko = kt*BKH;
    cp16(da + so0, aG0 + ko); cp16(db + so0, bG0 + ko);
    cp16(da + so1, aG1 + ko); cp16(db + so1, bG1 + ko);
  };

  auto compute = [&](auto stc){
    constexpr int S0 = decltype(stc)::value * TILE_B;
    {
      uint32_t ah[4][4];
      ldsm4o<S0>(ah[0][0], ah[0][1], ah[0][2], ah[0][3], aAddr[0]);
      ldsm4o<S0>(ah[1][0], ah[1][1], ah[1][2], ah[1][3], aAddr[1]);
      ldsm4o<S0>(ah[2][0], ah[2][1], ah[2][2], ah[2][3], aAddr[2]);
      ldsm4o<S0>(ah[3][0], ah[3][1], ah[3][2], ah[3][3], aAddr[3]);
      uint32_t bh[4][2];
      ldsm4o<S0>(bh[0][0], bh[1][0], bh[0][1], bh[1][1], bAddr[0]);
      ldsm4o<S0>(bh[2][0], bh[3][0], bh[2][1], bh[3][1], bAddr[1]);
      #pragma unroll
      for (int mi = 0; mi < 4; mi++)
        #pragma unroll
        for (int ni = 0; ni < 4; ni++)
          mma16(acc[mi][ni], ah[mi], bh[ni]);
    }
    {
      uint32_t ah[4][4];
      ldsm4o<S0+32>(ah[0][0], ah[0][1], ah[0][2], ah[0][3], aAddr[0]);
      ldsm4o<S0+32>(ah[1][0], ah[1][1], ah[1][2], ah[1][3], aAddr[1]);
      ldsm4o<S0+32>(ah[2][0], ah[2][1], ah[2][2], ah[2][3], aAddr[2]);
      ldsm4o<S0+32>(ah[3][0], ah[3][1], ah[3][2], ah[3][3], aAddr[3]);
      uint32_t bh[4][2];
      ldsm4o<S0+32>(bh[0][0], bh[1][0], bh[0][1], bh[1][1], bAddr[0]);
      ldsm4o<S0+32>(bh[2][0], bh[3][0], bh[2][1], bh[3][1], bAddr[1]);
      #pragma unroll
      for (int mi = 0; mi < 4; mi++)
        #pragma unroll
        for (int ni = 0; ni < 4; ni++)
          mma16(acc[mi][ni], ah[mi], bh[ni]);
    }
  };

  #pragma unroll
  for (int s = 0; s < STAGES-1; s++){
    if (s < KT) issue(s);
    cp_commit();
  }
  for (int kt = 0; kt < KT; kt += 4){
    cp_wait<STAGES-2>(); __syncthreads();
    if (kt + 3 < KT) issue(kt + 3);
    cp_commit();
    compute(IC<0>{});
    cp_wait<STAGES-2>(); __syncthreads();
    if (kt + 4 < KT) issue(kt + 4);
    cp_commit();
    compute(IC<1>{});
    cp_wait<STAGES-2>(); __syncthreads();
    if (kt + 5 < KT) issue(kt + 5);
    cp_commit();
    compute(IC<2>{});
    cp_wait<STAGES-2>(); __syncthreads();
    if (kt + 6 < KT) issue(kt + 6);
    cp_commit();
    compute(IC<3>{});
  }
}

#define ACC_INIT8(acc) \
  _Pragma("unroll") \
  for (int i=0;i<4;i++) \
    _Pragma("unroll") \
    for (int j=0;j<8;j++) \
      _Pragma("unroll") \
      for (int l=0;l<4;l++) (acc)[i][j][l]=0.f;

#define ACC_INIT4(acc) \
  _Pragma("unroll") \
  for (int i=0;i<4;i++) \
    _Pragma("unroll") \
    for (int j=0;j<4;j++) \
      _Pragma("unroll") \
      for (int l=0;l<4;l++) (acc)[i][j][l]=0.f;

// ------------------------- prep kernel (conv_x + rowsum-zero + W transpose) ----

__global__ __launch_bounds__(256) void prep_kernel(
    const float* __restrict__ x,
    const float* __restrict__ Wq, const float* __restrict__ Wk, const float* __restrict__ Wv)
{
  __shared__ float tb[32][33];
  const int bid = blockIdx.x;
  if (bid < (MTOT*EMB)/(256*4)){          // 4096 conv blocks
    if (bid < MTOT/256)
      g_rowsum[(size_t)bid*256 + threadIdx.x] = 0.f;
    size_t i = ((size_t)bid*256 + threadIdx.x)*4;
    float4 v = *(const float4*)(x + i);
    __half2* d = (__half2*)(g_x + i);
    d[0] = __floats2half2_rn(v.x, v.y);
    d[1] = __floats2half2_rn(v.z, v.w);
  } else {                                 // 384 transpose blocks
    const int b2 = bid - (MTOT*EMB)/(256*4);
    const int z  = b2 >> 7;
    const int rem = b2 & 127;
    const int nb = rem & 15;
    const int kb = rem >> 4;
    const float* W = (z==0) ? Wq : (z==1) ? Wk : Wv;
    __half* WT = g_wt + (size_t)z*QD*EMB;
    const int tx = threadIdx.x & 31, ty = threadIdx.x >> 5;
    int n  = nb*32 + tx;
    int k0 = kb*32;
    #pragma unroll
    for (int j = ty; j < 32; j += 8)
      tb[j][tx] = W[(size_t)(k0 + j)*QD + n];
    __syncthreads();
    int n0 = nb*32;
    int k  = k0 + tx;
    #pragma unroll
    for (int j = ty; j < 32; j += 8)
      WT[(size_t)(n0 + j)*EMB + k] = __float2half(tb[tx][j]);
  }
}

// ------------------------- GEMM kernels -------------------------

// q/k projections (blockIdx.z = 0 -> q with sigmoid, 1 -> k)
__global__ __launch_bounds__(256, 2) void proj_qk_kernel(
    const float* __restrict__ bq, const float* __restrict__ bk)
{
  extern __shared__ char smem[];
  const int z = blockIdx.z;
  const int m0 = blockIdx.y*128, n0 = blockIdx.x*128;
  const __half* A = g_x  + (size_t)m0*EMB;
  const __half* B = g_wt + (size_t)z*QD*EMB + (size_t)n0*EMB;
  const float* bias = (z==0) ? bq : bk;

  float acc[4][4][4];
  ACC_INIT4(acc)

  gemm_fp16_core256(A, EMB, B, EMB, EMB/BKH, smem, acc);

  const int lane = threadIdx.x & 31, warp = threadIdx.x >> 5;
  const int rowL = (warp&1)*64 + (lane>>2);
  const int colL = (warp>>1)*32 + (lane&3)*2;

  __half* C = (z==0) ? g_q : g_k;
  #pragma unroll
  for (int mi=0; mi<4; mi++){
    #pragma unroll
    for (int ni=0; ni<4; ni++){
      int c0 = colL + ni*8;
      float b0 = bias[n0 + c0], b1 = bias[n0 + c0 + 1];
      #pragma unroll
      for (int h=0; h<2; h++){
        int r = m0 + rowL + mi*16 + h*8;
        float v0 = acc[mi][ni][h*2+0] + b0;
        float v1 = acc[mi][ni][h*2+1] + b1;
        if (z==0){ v0 = 1.f/(1.f+__expf(-v0)); v1 = 1.f/(1.f+__expf(-v1)); }
        *(__half2*)(C + (size_t)r*QD + n0 + c0) = __floats2half2_rn(v0, v1);
      }
    }
  }
}

// v projection, writes V^T (runs on a parallel stream, overlapped with qk)
__global__ __launch_bounds__(256, 2) void proj_v_kernel(const float* __restrict__ bv)
{
  extern __shared__ char smem[];
  const int m0 = blockIdx.y*128, n0 = blockIdx.x*128;
  const __half* A = g_x  + (size_t)m0*EMB;
  const __half* B = g_wt + (size_t)2*QD*EMB + (size_t)n0*EMB;

  float acc[4][4][4];
  ACC_INIT4(acc)

  gemm_fp16_core256(A, EMB, B, EMB, EMB/BKH, smem, acc);

  const int lane = threadIdx.x & 31, warp = threadIdx.x >> 5;
  const int rowL = (warp&1)*64 + (lane>>2);
  const int colL = (warp>>1)*32 + (lane&3)*2;

  __syncthreads();
  __half* tr = (__half*)smem;      // 128*136*2 = 34816 B <= 81920
  #pragma unroll
  for (int mi=0; mi<4; mi++){
    #pragma unroll
    for (int ni=0; ni<4; ni++){
      int c0 = colL + ni*8;
      float b0 = bv[n0 + c0], b1 = bv[n0 + c0 + 1];
      #pragma unroll
      for (int h=0; h<2; h++){
        int r = rowL + mi*16 + h*8;
        tr[(c0  )*136 + r] = __float2half(acc[mi][ni][h*2+0] + b0);
        tr[(c0+1)*136 + r] = __float2half(acc[mi][ni][h*2+1] + b1);
      }
    }
  }
  __syncthreads();
  const int bb = m0 >> 11;
  const int s0 = m0 & 2047;
  #pragma unroll
  for (int it = 0; it < 16; it++){
    int c = it*8 + warp;
    uint2 val = *(uint2*)&tr[c*136 + lane*4];
    *(uint2*)(g_vt + ((size_t)bb*VD + n0 + c)*SEQ + s0 + lane*4) = val;
  }
}

// qk: logits -> elu -> exp (UNNORMALIZED softmax numerator, fp16) + row sums.
__global__ __launch_bounds__(GTHR, 2) void qk_kernel()
{
  extern __shared__ char smem[];
  const int b = blockIdx.z;
  const int m0 = blockIdx.y*128, n0 = blockIdx.x*128;
  const __half* A = g_q + (size_t)b*SEQ*QD + (size_t)m0*QD;
  const __half* B = g_k + (size_t)b*SEQ*QD + (size_t)n0*QD;

  float acc[4][8][4];
  ACC_INIT8(acc)

  gemm_fp16_core(A, QD, B, QD, QD/BKH, smem, acc);

  __half* P = g_p + (size_t)b*SEQ*SEQ;
  const int lane = threadIdx.x & 31, warp = threadIdx.x >> 5;
  const int rowB = m0 + (warp&1)*64 + (lane>>2);
  const int colB = n0 + (warp>>1)*64 + (lane&3)*2;
  const float scale = 0.0625f;   // 1/sqrt(256)

  float rsum[4][2];
  #pragma unroll
  for (int mi=0; mi<4; mi++){ rsum[mi][0]=0.f; rsum[mi][1]=0.f; }

  #pragma unroll
  for (int mi=0; mi<4; mi++){
    #pragma unroll
    for (int ni=0; ni<8; ni++){
      int c0 = colB + ni*8;
      #pragma unroll
      for (int h=0; h<2; h++){
        int r = rowB + mi*16 + h*8;
        float v0 = acc[mi][ni][h*2+0] * scale;
        float v1 = acc[mi][ni][h*2+1] * scale;
        float p0 = (v0 > 0.f) ? __expf(v0) : __expf(__expf(v0) - 1.f);
        float p1 = (v1 > 0.f) ? __expf(v1) : __expf(__expf(v1) - 1.f);
        *(__half2*)(P + (size_t)r*SEQ + c0) = __floats2half2_rn(p0, p1);
        rsum[mi][h] += p0 + p1;
      }
    }
  }

  #pragma unroll
  for (int mi=0; mi<4; mi++){
    #pragma unroll
    for (int h=0; h<2; h++){
      float s = rsum[mi][h];
      s += __shfl_xor_sync(0xffffffffu, s, 1);
      s += __shfl_xor_sync(0xffffffffu, s, 2);
      if ((lane & 3) == 0){
        int r = rowB + mi*16 + h*8;
        atomicAdd(&g_rowsum[(size_t)b*SEQ + r], s);
      }
    }
  }
}

__global__ __launch_bounds__(GTHR, 2) void pv_kernel(float* __restrict__ out)
{
  extern __shared__ char smem[];
  const int b = blockIdx.z;
  const int m0 = blockIdx.y*128, n0 = blockIdx.x*128;
  const __half* A = g_p  + (size_t)b*SEQ*SEQ + (size_t)m0*SEQ;
  const __half* B = g_vt + (size_t)b*VD*SEQ  + (size_t)n0*SEQ;
  float* O        = out  + (size_t)b*SEQ*VD;

  float acc[4][8][4];
  ACC_INIT8(acc)

  gemm_fp16_core(A, SEQ, B, SEQ, SEQ/BKH, smem, acc);

  const int lane = threadIdx.x & 31, warp = threadIdx.x >> 5;
  const int rowB = m0 + (warp&1)*64 + (lane>>2);
  const int colB = n0 + (warp>>1)*64 + (lane&3)*2;

  float inv[4][2];
  #pragma unroll
  for (int mi=0; mi<4; mi++)
    #pragma unroll
    for (int h=0; h<2; h++)
      inv[mi][h] = 1.f / g_rowsum[(size_t)b*SEQ + rowB + mi*16 + h*8];

  #pragma unroll
  for (int mi=0; mi<4; mi++){
    #pragma unroll
    for (int ni=0; ni<8; ni++){
      int c0 = colB + ni*8;
      #pragma unroll
      for (int h=0; h<2; h++){
        int r = rowB + mi*16 + h*8;
        *(float2*)(O + (size_t)r*VD + c0) =
            make_float2(acc[mi][ni][h*2+0]*inv[mi][h], acc[mi][ni][h*2+1]*inv[mi][h]);
      }
    }
  }
}

// ------------------------- launch -------------------------

extern "C" void kernel_launch(void* const* d_in, const int* in_sizes, int n_in,
                              void* d_out, int out_size)
{
  (void)in_sizes; (void)n_in; (void)out_size;
  const float* x  = (const float*)d_in[0];
  const float* Wq = (const float*)d_in[1];
  const float* bq = (const float*)d_in[2];
  const float* Wk = (const float*)d_in[3];
  const float* bk = (const float*)d_in[4];
  const float* Wv = (const float*)d_in[5];
  const float* bv = (const float*)d_in[6];
  float* out = (float*)d_out;

  static cudaStream_t s1 = nullptr;
  static cudaEvent_t  eP = nullptr, eV = nullptr;
  if (!s1){
    // created on the first (uncaptured) correctness call; reused under capture
    cudaStreamCreateWithFlags(&s1, cudaStreamNonBlocking);
    cudaEventCreateWithFlags(&eP, cudaEventDisableTiming);
    cudaEventCreateWithFlags(&eV, cudaEventDisableTiming);
    cudaFuncSetAttribute(proj_qk_kernel, cudaFuncAttributeMaxDynamicSharedMemorySize, GSMEM);
    cudaFuncSetAttribute(proj_v_kernel,  cudaFuncAttributeMaxDynamicSharedMemorySize, GSMEM);
    cudaFuncSetAttribute(qk_kernel,      cudaFuncAttributeMaxDynamicSharedMemorySize, GSMEM);
    cudaFuncSetAttribute(pv_kernel,      cudaFuncAttributeMaxDynamicSharedMemorySize, GSMEM);
  }

  // main stream: prep -> proj_qk -> qk -> (join) -> pv
  prep_kernel<<<(MTOT*EMB)/(256*4) + 384, 256>>>(x, Wq, Wk, Wv);
  cudaEventRecord(eP, 0);

  // fork: v-projection runs concurrently with proj_qk / qk
  cudaStreamWaitEvent(s1, eP, 0);
  proj_v_kernel<<<dim3(QD/128, MTOT/128), 256, GSMEM, s1>>>(bv);
  cudaEventRecord(eV, s1);

  proj_qk_kernel<<<dim3(QD/128, MTOT/128, 2), 256, GSMEM>>>(bq, bk);

  qk_kernel<<<dim3(SEQ/128, SEQ/128, BATCH), GTHR, GSMEM>>>();

  // join: pv needs both qk (stream order) and proj_v (event)
  cudaStreamWaitEvent(0, eV, 0);
  pv_kernel<<<dim3(VD/128, SEQ/128, BATCH), GTHR, GSMEM>>>(out);
}

// round 17
// speedup vs baseline: 1.0248x; 1.0248x over previous
#include <cuda_runtime.h>
#include <cuda_fp16.h>
#include <cstdint>

#define BATCH 8
#define SEQ   2048
#define EMB   256
#define QD    512
#define VD    512
#define MTOT  (BATCH*SEQ)   // 16384

#define BKH    32                 // k-elements (halfs) per tile
#define STAGES 4
#define ROWB   80                 // smem row bytes: 64 data + 16 pad (conflict-free)
#define TILE_B (128*ROWB)         // 10240 B per stage per operand
#define GSMEM  (STAGES*2*TILE_B)  // 81920 B
#define GTHR   128                // qk/pv: 4 warps, 2x2 grid of 64x64 warp tiles

// ---------------- scratch (device globals; allocation-free) ----------------
__device__ __half g_x [(size_t)MTOT*EMB];        // x in fp16
__device__ __half g_wt[(size_t)3*QD*EMB];        // W^T fp16: [z][n][k]
__device__ __half g_q [(size_t)MTOT*QD];
__device__ __half g_k [(size_t)MTOT*QD];
__device__ __half g_vt[(size_t)BATCH*VD*SEQ];    // V^T fp16: [b][v][s]
__device__ __half g_p [(size_t)BATCH*SEQ*SEQ];   // UNNORMALIZED probs fp16
__device__ float  g_rowsum[(size_t)MTOT];        // per-row sum of exp

// ---------------- helpers ----------------
__device__ __forceinline__ void mma16(float c[4], const uint32_t a[4], const uint32_t b[2]){
  asm volatile(
    "mma.sync.aligned.m16n8k16.row.col.f32.f16.f16.f32 "
    "{%0,%1,%2,%3}, {%4,%5,%6,%7}, {%8,%9}, {%0,%1,%2,%3};"
    : "+f"(c[0]), "+f"(c[1]), "+f"(c[2]), "+f"(c[3])
    : "r"(a[0]), "r"(a[1]), "r"(a[2]), "r"(a[3]), "r"(b[0]), "r"(b[1]));
}
__device__ __forceinline__ void ldsm4(uint32_t& r0, uint32_t& r1, uint32_t& r2, uint32_t& r3,
                                      uint32_t addr){
  asm volatile("ldmatrix.sync.aligned.m8n8.x4.shared.b16 {%0,%1,%2,%3}, [%4];"
    : "=r"(r0), "=r"(r1), "=r"(r2), "=r"(r3) : "r"(addr));
}
__device__ __forceinline__ void cp16(uint32_t dst, const void* src){
  asm volatile("cp.async.ca.shared.global [%0], [%1], 16;" :: "r"(dst), "l"(src) : "memory");
}
__device__ __forceinline__ void cp_commit(){
  asm volatile("cp.async.commit_group;" ::: "memory");
}
template<int N> __device__ __forceinline__ void cp_wait(){
  asm volatile("cp.async.wait_group %0;" :: "n"(N) : "memory");
}

// ---------------- fp16 GEMM core, 128 threads (qk/pv) -------------------------
// C[128,128] = A[128,K] @ B[128,K]^T.  2x2 warp grid, 64x64 warp tiles.
// ldmatrix fragment loads; address bases hoisted; st/ks folded via 4x unroll.
__device__ __forceinline__ void gemm_fp16_core(
    const __half* __restrict__ A, int lda,
    const __half* __restrict__ B, int ldb,
    int KT, char* smem, float acc[4][8][4])
{
  const int tid  = threadIdx.x;
  const int lane = tid & 31, warp = tid >> 5;
  const int mB = (warp & 1)*64, nB = (warp >> 1)*64;
  const int lrow  = lane & 15;
  const int lkoff = (lane >> 4)*16;

  const uint32_t sA = (uint32_t)__cvta_generic_to_shared(smem);
  const uint32_t sB = sA + STAGES*TILE_B;

  // hoisted ldmatrix base addresses (loop-invariant)
  uint32_t aAddr[4], bAddr[4];
  #pragma unroll
  for (int mi = 0; mi < 4; mi++)
    aAddr[mi] = sA + (mB + mi*16 + lrow)*ROWB + lkoff;
  #pragma unroll
  for (int nn = 0; nn < 4; nn++)
    bAddr[nn] = sB + (nB + nn*16 + lrow)*ROWB + lkoff;

  // hoisted cp.async coordinates: per-thread global bases + smem offsets
  const int cr0 = tid >> 2, cc0 = (tid & 3);         // chunk 0
  const __half* aG0 = A + (size_t)cr0*lda + cc0*8;
  const __half* bG0 = B + (size_t)cr0*ldb + cc0*8;
  const int cr1 = (tid + 128) >> 2, cc1 = ((tid + 128) & 3);
  const __half* aG1 = A + (size_t)cr1*lda + cc1*8;
  const __half* bG1 = B + (size_t)cr1*ldb + cc1*8;
  const int cr2 = (tid + 256) >> 2, cc2 = ((tid + 256) & 3);
  const __half* aG2 = A + (size_t)cr2*lda + cc2*8;
  const __half* bG2 = B + (size_t)cr2*ldb + cc2*8;
  const int cr3 = (tid + 384) >> 2, cc3 = ((tid + 384) & 3);
  const __half* aG3 = A + (size_t)cr3*lda + cc3*8;
  const __half* bG3 = B + (size_t)cr3*ldb + cc3*8;
  const uint32_t so0 = cr0*ROWB + cc0*16;
  const uint32_t so1 = cr1*ROWB + cc1*16;
  const uint32_t so2 = cr2*ROWB + cc2*16;
  const uint32_t so3 = cr3*ROWB + cc3*16;

  auto issue = [&](int kt){
    int st = kt & (STAGES-1);
    uint32_t da = sA + st*TILE_B, db = sB + st*TILE_B;
    int ko = kt*BKH;
    cp16(da + so0, aG0 + ko); cp16(db + so0, bG0 + ko);
    cp16(da + so1, aG1 + ko); cp16(db + so1, bG1 + ko);
    cp16(da + so2, aG2 + ko); cp16(db + so2, bG2 + ko);
    cp16(da + so3, aG3 + ko); cp16(db + so3, bG3 + ko);
  };

  auto compute = [&](int stOff){         // stOff = st*TILE_B (compile-time after unroll)
    #pragma unroll
    for (int ks = 0; ks < 2; ks++){
      const uint32_t kb = stOff + ks*32;
      uint32_t ah[4][4];
      #pragma unroll
      for (int mi = 0; mi < 4; mi++)
        ldsm4(ah[mi][0], ah[mi][1], ah[mi][2], ah[mi][3], aAddr[mi] + kb);
      uint32_t bh[8][2];
      #pragma unroll
      for (int nn = 0; nn < 4; nn++)
        ldsm4(bh[nn*2][0], bh[nn*2+1][0], bh[nn*2][1], bh[nn*2+1][1], bAddr[nn] + kb);
      #pragma unroll
      for (int mi = 0; mi < 4; mi++)
        #pragma unroll
        for (int ni = 0; ni < 8; ni++)
          mma16(acc[mi][ni], ah[mi], bh[ni]);
    }
  };

  #pragma unroll
  for (int s = 0; s < STAGES-1; s++){
    if (s < KT) issue(s);
    cp_commit();
  }
  #pragma unroll 4
  for (int kt = 0; kt < KT; kt++){
    cp_wait<STAGES-2>();
    __syncthreads();
    if (kt + STAGES-1 < KT) issue(kt + STAGES-1);
    cp_commit();
    compute((kt & (STAGES-1))*TILE_B);
  }
}

// ---------------- fp16 GEMM core, 256 threads (proj: short K) -----------------
__device__ __forceinline__ void gemm_fp16_core256(
    const __half* __restrict__ A, int lda,
    const __half* __restrict__ B, int ldb,
    int KT, char* smem, float acc[4][4][4])
{
  const int tid  = threadIdx.x;
  const int lane = tid & 31, warp = tid >> 5;
  const int mB = (warp & 1)*64, nB = (warp >> 1)*32;
  const int lrow  = lane & 15;
  const int lkoff = (lane >> 4)*16;

  const uint32_t sA = (uint32_t)__cvta_generic_to_shared(smem);
  const uint32_t sB = sA + STAGES*TILE_B;

  uint32_t aAddr[4], bAddr[2];
  #pragma unroll
  for (int mi = 0; mi < 4; mi++)
    aAddr[mi] = sA + (mB + mi*16 + lrow)*ROWB + lkoff;
  #pragma unroll
  for (int nn = 0; nn < 2; nn++)
    bAddr[nn] = sB + (nB + nn*16 + lrow)*ROWB + lkoff;

  const int cr0 = tid >> 2, cc0 = (tid & 3);
  const __half* aG0 = A + (size_t)cr0*lda + cc0*8;
  const __half* bG0 = B + (size_t)cr0*ldb + cc0*8;
  const int cr1 = (tid + 256) >> 2, cc1 = ((tid + 256) & 3);
  const __half* aG1 = A + (size_t)cr1*lda + cc1*8;
  const __half* bG1 = B + (size_t)cr1*ldb + cc1*8;
  const uint32_t so0 = cr0*ROWB + cc0*16;
  const uint32_t so1 = cr1*ROWB + cc1*16;

  auto issue = [&](int kt){
    int st = kt & (STAGES-1);
    uint32_t da = sA + st*TILE_B, db = sB + st*TILE_B;
    int ko = kt*BKH;
    cp16(da + so0, aG0 + ko); cp16(db + so0, bG0 + ko);
    cp16(da + so1, aG1 + ko); cp16(db + so1, bG1 + ko);
  };

  auto compute = [&](int stOff){
    #pragma unroll
    for (int ks = 0; ks < 2; ks++){
      const uint32_t kb = stOff + ks*32;
      uint32_t ah[4][4];
      #pragma unroll
      for (int mi = 0; mi < 4; mi++)
        ldsm4(ah[mi][0], ah[mi][1], ah[mi][2], ah[mi][3], aAddr[mi] + kb);
      uint32_t bh[4][2];
      #pragma unroll
      for (int nn = 0; nn < 2; nn++)
        ldsm4(bh[nn*2][0], bh[nn*2+1][0], bh[nn*2][1], bh[nn*2+1][1], bAddr[nn] + kb);
      #pragma unroll
      for (int mi = 0; mi < 4; mi++)
        #pragma unroll
        for (int ni = 0; ni < 4; ni++)
          mma16(acc[mi][ni], ah[mi], bh[ni]);
    }
  };

  #pragma unroll
  for (int s = 0; s < STAGES-1; s++){
    if (s < KT) issue(s);
    cp_commit();
  }
  #pragma unroll 4
  for (int kt = 0; kt < KT; kt++){
    cp_wait<STAGES-2>();
    __syncthreads();
    if (kt + STAGES-1 < KT) issue(kt + STAGES-1);
    cp_commit();
    compute((kt & (STAGES-1))*TILE_B);
  }
}

#define ACC_INIT8(acc) \
  _Pragma("unroll") \
  for (int i=0;i<4;i++) \
    _Pragma("unroll") \
    for (int j=0;j<8;j++) \
      _Pragma("unroll") \
      for (int l=0;l<4;l++) (acc)[i][j][l]=0.f;

#define ACC_INIT4(acc) \
  _Pragma("unroll") \
  for (int i=0;i<4;i++) \
    _Pragma("unroll") \
    for (int j=0;j<4;j++) \
      _Pragma("unroll") \
      for (int l=0;l<4;l++) (acc)[i][j][l]=0.f;

// ------------------------- prep kernels -------------------------

__global__ __launch_bounds__(256) void conv_x_kernel(const float* __restrict__ x){
  if (blockIdx.x < MTOT/256)
    g_rowsum[(size_t)blockIdx.x*256 + threadIdx.x] = 0.f;
  size_t i = ((size_t)blockIdx.x*256 + threadIdx.x)*4;
  float4 v = *(const float4*)(x + i);
  __half2* d = (__half2*)(g_x + i);
  d[0] = __floats2half2_rn(v.x, v.y);
  d[1] = __floats2half2_rn(v.z, v.w);
}

__global__ __launch_bounds__(256) void transpose_w_kernel(
    const float* __restrict__ Wq, const float* __restrict__ Wk, const float* __restrict__ Wv)
{
  __shared__ float tb[32][33];
  const int z = blockIdx.z;
  const float* W = (z==0) ? Wq : (z==1) ? Wk : Wv;
  __half* WT = g_wt + (size_t)z*QD*EMB;
  int n  = blockIdx.x*32 + threadIdx.x;
  int k0 = blockIdx.y*32;
  #pragma unroll
  for (int j = threadIdx.y; j < 32; j += 8)
    tb[j][threadIdx.x] = W[(size_t)(k0 + j)*QD + n];
  __syncthreads();
  int n0 = blockIdx.x*32;
  int k  = k0 + threadIdx.x;
  #pragma unroll
  for (int j = threadIdx.y; j < 32; j += 8)
    WT[(size_t)(n0 + j)*EMB + k] = __float2half(tb[threadIdx.x][j]);
}

// ------------------------- GEMM kernels -------------------------

__global__ __launch_bounds__(256, 2) void proj_kernel(
    const float* __restrict__ bq, const float* __restrict__ bk, const float* __restrict__ bv)
{
  extern __shared__ char smem[];
  const int z = blockIdx.z;
  const int m0 = blockIdx.y*128, n0 = blockIdx.x*128;
  const __half* A = g_x  + (size_t)m0*EMB;
  const __half* B = g_wt + (size_t)z*QD*EMB + (size_t)n0*EMB;
  const float* bias = (z==0) ? bq : (z==1) ? bk : bv;

  float acc[4][4][4];
  ACC_INIT4(acc)

  gemm_fp16_core256(A, EMB, B, EMB, EMB/BKH, smem, acc);

  const int lane = threadIdx.x & 31, warp = threadIdx.x >> 5;
  const int rowL = (warp&1)*64 + (lane>>2);
  const int colL = (warp>>1)*32 + (lane&3)*2;

  if (z < 2){
    __half* C = (z==0) ? g_q : g_k;
    #pragma unroll
    for (int mi=0; mi<4; mi++){
      #pragma unroll
      for (int ni=0; ni<4; ni++){
        int c0 = colL + ni*8;
        float b0 = bias[n0 + c0], b1 = bias[n0 + c0 + 1];
        #pragma unroll
        for (int h=0; h<2; h++){
          int r = m0 + rowL + mi*16 + h*8;
          float v0 = acc[mi][ni][h*2+0] + b0;
          float v1 = acc[mi][ni][h*2+1] + b1;
          if (z==0){ v0 = 1.f/(1.f+__expf(-v0)); v1 = 1.f/(1.f+__expf(-v1)); }
          *(__half2*)(C + (size_t)r*QD + n0 + c0) = __floats2half2_rn(v0, v1);
        }
      }
    }
  } else {
    __syncthreads();
    __half* tr = (__half*)smem;      // 128*136*2 = 34816 B <= 81920
    #pragma unroll
    for (int mi=0; mi<4; mi++){
      #pragma unroll
      for (int ni=0; ni<4; ni++){
        int c0 = colL + ni*8;
        float b0 = bias[n0 + c0], b1 = bias[n0 + c0 + 1];
        #pragma unroll
        for (int h=0; h<2; h++){
          int r = rowL + mi*16 + h*8;
          tr[(c0  )*136 + r] = __float2half(acc[mi][ni][h*2+0] + b0);
          tr[(c0+1)*136 + r] = __float2half(acc[mi][ni][h*2+1] + b1);
        }
      }
    }
    __syncthreads();
    const int bb = m0 >> 11;
    const int s0 = m0 & 2047;
    #pragma unroll
    for (int it = 0; it < 16; it++){
      int c = it*8 + warp;
      uint2 val = *(uint2*)&tr[c*136 + lane*4];
      *(uint2*)(g_vt + ((size_t)bb*VD + n0 + c)*SEQ + s0 + lane*4) = val;
    }
  }
}

// qk: logits -> elu -> exp (UNNORMALIZED softmax numerator, fp16) + row sums.
__global__ __launch_bounds__(GTHR, 2) void qk_kernel()
{
  extern __shared__ char smem[];
  const int b = blockIdx.z;
  const int m0 = blockIdx.y*128, n0 = blockIdx.x*128;
  const __half* A = g_q + (size_t)b*SEQ*QD + (size_t)m0*QD;
  const __half* B = g_k + (size_t)b*SEQ*QD + (size_t)n0*QD;

  float acc[4][8][4];
  ACC_INIT8(acc)

  gemm_fp16_core(A, QD, B, QD, QD/BKH, smem, acc);

  __half* P = g_p + (size_t)b*SEQ*SEQ;
  const int lane = threadIdx.x & 31, warp = threadIdx.x >> 5;
  const int rowB = m0 + (warp&1)*64 + (lane>>2);
  const int colB = n0 + (warp>>1)*64 + (lane&3)*2;
  const float scale = 0.0625f;   // 1/sqrt(256)

  float rsum[4][2];
  #pragma unroll
  for (int mi=0; mi<4; mi++){ rsum[mi][0]=0.f; rsum[mi][1]=0.f; }

  #pragma unroll
  for (int mi=0; mi<4; mi++){
    #pragma unroll
    for (int ni=0; ni<8; ni++){
      int c0 = colB + ni*8;
      #pragma unroll
      for (int h=0; h<2; h++){
        int r = rowB + mi*16 + h*8;
        float v0 = acc[mi][ni][h*2+0] * scale;
        float v1 = acc[mi][ni][h*2+1] * scale;
        float p0 = (v0 > 0.f) ? __expf(v0) : __expf(__expf(v0) - 1.f);
        float p1 = (v1 > 0.f) ? __expf(v1) : __expf(__expf(v1) - 1.f);
        *(__half2*)(P + (size_t)r*SEQ + c0) = __floats2half2_rn(p0, p1);
        rsum[mi][h] += p0 + p1;
      }
    }
  }

  #pragma unroll
  for (int mi=0; mi<4; mi++){
    #pragma unroll
    for (int h=0; h<2; h++){
      float s = rsum[mi][h];
      s += __shfl_xor_sync(0xffffffffu, s, 1);
      s += __shfl_xor_sync(0xffffffffu, s, 2);
      if ((lane & 3) == 0){
        int r = rowB + mi*16 + h*8;
        atomicAdd(&g_rowsum[(size_t)b*SEQ + r], s);
      }
    }
  }
}

__global__ __launch_bounds__(GTHR, 2) void pv_kernel(float* __restrict__ out)
{
  extern __shared__ char smem[];
  const int b = blockIdx.z;
  const int m0 = blockIdx.y*128, n0 = blockIdx.x*128;
  const __half* A = g_p  + (size_t)b*SEQ*SEQ + (size_t)m0*SEQ;
  const __half* B = g_vt + (size_t)b*VD*SEQ  + (size_t)n0*SEQ;
  float* O        = out  + (size_t)b*SEQ*VD;

  float acc[4][8][4];
  ACC_INIT8(acc)

  gemm_fp16_core(A, SEQ, B, SEQ, SEQ/BKH, smem, acc);

  const int lane = threadIdx.x & 31, warp = threadIdx.x >> 5;
  const int rowB = m0 + (warp&1)*64 + (lane>>2);
  const int colB = n0 + (warp>>1)*64 + (lane&3)*2;

  float inv[4][2];
  #pragma unroll
  for (int mi=0; mi<4; mi++)
    #pragma unroll
    for (int h=0; h<2; h++)
      inv[mi][h] = 1.f / g_rowsum[(size_t)b*SEQ + rowB + mi*16 + h*8];

  #pragma unroll
  for (int mi=0; mi<4; mi++){
    #pragma unroll
    for (int ni=0; ni<8; ni++){
      int c0 = colB + ni*8;
      #pragma unroll
      for (int h=0; h<2; h++){
        int r = rowB + mi*16 + h*8;
        *(float2*)(O + (size_t)r*VD + c0) =
            make_float2(acc[mi][ni][h*2+0]*inv[mi][h], acc[mi][ni][h*2+1]*inv[mi][h]);
      }
    }
  }
}

// ------------------------- launch -------------------------

extern "C" void kernel_launch(void* const* d_in, const int* in_sizes, int n_in,
                              void* d_out, int out_size)
{
  (void)in_sizes; (void)n_in; (void)out_size;
  const float* x  = (const float*)d_in[0];
  const float* Wq = (const float*)d_in[1];
  const float* bq = (const float*)d_in[2];
  const float* Wk = (const float*)d_in[3];
  const float* bk = (const float*)d_in[4];
  const float* Wv = (const float*)d_in[5];
  const float* bv = (const float*)d_in[6];
  float* out = (float*)d_out;

  static bool attr_done = false;
  if (!attr_done){
    cudaFuncSetAttribute(proj_kernel, cudaFuncAttributeMaxDynamicSharedMemorySize, GSMEM);
    cudaFuncSetAttribute(qk_kernel,   cudaFuncAttributeMaxDynamicSharedMemorySize, GSMEM);
    cudaFuncSetAttribute(pv_kernel,   cudaFuncAttributeMaxDynamicSharedMemorySize, GSMEM);
    attr_done = true;
  }

  conv_x_kernel<<<(MTOT*EMB)/(256*4), 256>>>(x);
  transpose_w_kernel<<<dim3(QD/32, EMB/32, 3), dim3(32, 8)>>>(Wq, Wk, Wv);

  proj_kernel<<<dim3(QD/128, MTOT/128, 3), 256, GSMEM>>>(bq, bk, bv);

  qk_kernel<<<dim3(SEQ/128, SEQ/128, BATCH), GTHR, GSMEM>>>();

  pv_kernel<<<dim3(VD/128, SEQ/128, BATCH), GTHR, GSMEM>>>(out);
}